// round 12
// baseline (speedup 1.0000x reference)
#include <cuda_runtime.h>

#define PI_F 3.14159265358979f

typedef unsigned long long u64;
struct P { u64 v; };

__device__ __forceinline__ P mkP(u64 x){ P r; r.v = x; return r; }
__device__ __forceinline__ P pack2(float lo, float hi){
    P r; asm("mov.b64 %0,{%1,%2};" : "=l"(r.v) : "f"(lo), "f"(hi)); return r;
}
__device__ __forceinline__ P dupP(float v){
    P r; asm("mov.b64 %0,{%1,%1};" : "=l"(r.v) : "f"(v)); return r;
}
__device__ __forceinline__ void unpack2(P a, float& lo, float& hi){
    asm("mov.b64 {%0,%1},%2;" : "=f"(lo), "=f"(hi) : "l"(a.v));
}
__device__ __forceinline__ P fma2(P a, P b, P c){
    P r; asm("fma.rn.f32x2 %0,%1,%2,%3;" : "=l"(r.v) : "l"(a.v), "l"(b.v), "l"(c.v)); return r;
}
#define K_ZERO (mkP(0ULL))
__device__ __forceinline__ P mul2(P a, P b){ return fma2(a, b, K_ZERO); }

// shared layout (floats). MLP weights TRANSPOSED, adjacent-neuron pairs.
#define OFF_W1   0      // 64
#define OFF_B1   64     // 16
#define OFF_W2   80     // 512
#define OFF_B2   592    // 32
#define OFF_W3   624    // 512
#define OFF_B3   1136   // 16
#define OFF_C    1152   // 60 (30 pair-duplicated Heisenberg coefficients)
#define SW_TOTAL 1216

#define BLK 160

// Quantum encoder for one packed batch-pair (lane0=A, lane1=B).
__device__ __forceinline__ void quantum_pair(
    const float* __restrict__ xA, const float* __restrict__ xB,
    const float* __restrict__ sw, P* __restrict__ eo)
{
    P bz[4], bx[4], by[4];
#pragma unroll
    for (int i = 0; i < 4; i++) {
        float sA, cA, sB, cB, pA, qA, pB, qB;
        __sincosf(xA[i] * PI_F, &sA, &cA);
        __sincosf(xB[i] * PI_F, &sB, &cB);
        __sincosf(xA[i+4] * PI_F, &pA, &qA);
        __sincosf(xB[i+4] * PI_F, &pB, &qB);
        bz[i] = pack2(cA, cB);
        P sp = pack2(sA, sB);
        bx[i] = mul2(sp, pack2(qA, qB));
        by[i] = mul2(sp, pack2(pA, pB));
    }
    const P* Kp = (const P*)(sw + OFF_C);

    P a_ = mul2(bx[0], bx[1]);
    P b_ = mul2(bx[1], bx[2]);
    P c_ = mul2(bx[0], bx[2]);
    P d_ = mul2(by[0], by[1]);
    P e_ = mul2(by[1], by[2]);
    P f_ = mul2(bx[2], bx[3]);
    P h_ = mul2(bx[0], bx[3]);
    P i_ = mul2(bz[0], bz[2]);
    P j_ = mul2(by[2], by[3]);
    P k_ = mul2(bz[1], bz[3]);
    P l_ = mul2(bz[0], bx[1]);
    P m_ = mul2(by[0], bz[1]);
    P u_ = mul2(bz[0], b_);
    P v_ = mul2(a_, bz[2]);
    P w_ = mul2(m_, by[2]);

    eo[0] = fma2(Kp[1], a_, mul2(Kp[0], bz[0]));

    P e1 = fma2(Kp[3], u_, mul2(Kp[2], bz[1]));
    e1 = fma2(Kp[4], d_, e1);
    eo[1] = fma2(Kp[5], c_, e1);

    P e2 = mul2(Kp[6], i_);
    e2 = fma2(Kp[7],  mul2(bz[1], f_), e2);
    e2 = fma2(Kp[8],  e_, e2);
    e2 = fma2(Kp[9],  mul2(l_, bx[3]), e2);
    e2 = fma2(Kp[10], v_, e2);
    e2 = fma2(Kp[11], mul2(d_, f_), e2);
    e2 = fma2(Kp[12], w_, e2);
    eo[2] = fma2(Kp[13], h_, e2);

    P e3 = mul2(Kp[14], k_);
    e3 = fma2(Kp[15], mul2(i_, bx[3]), e3);
    e3 = fma2(Kp[16], mul2(bz[0], j_), e3);
    e3 = fma2(Kp[17], mul2(bz[1], bx[2]), e3);
    e3 = fma2(Kp[18], mul2(u_, bz[3]), e3);
    e3 = fma2(Kp[19], mul2(e_, bx[3]), e3);
    e3 = fma2(Kp[20], mul2(mul2(by[1], bz[2]), by[3]), e3);
    e3 = fma2(Kp[21], l_, e3);
    e3 = fma2(Kp[22], mul2(d_, bz[3]), e3);
    e3 = fma2(Kp[23], mul2(v_, bx[3]), e3);
    e3 = fma2(Kp[24], mul2(a_, j_), e3);
    e3 = fma2(Kp[25], mul2(d_, bx[2]), e3);
    e3 = fma2(Kp[26], mul2(c_, bz[3]), e3);
    e3 = fma2(Kp[27], mul2(w_, bx[3]), e3);
    e3 = fma2(Kp[28], mul2(mul2(m_, bz[2]), by[3]), e3);
    eo[3] = fma2(Kp[29], bx[0], e3);
}

__global__ __launch_bounds__(BLK, 2) void hqae_kernel(
    const float* __restrict__ x,  const float* __restrict__ qw,
    const float* __restrict__ W1, const float* __restrict__ b1,
    const float* __restrict__ W2, const float* __restrict__ b2,
    const float* __restrict__ W3, const float* __restrict__ b3,
    float* __restrict__ out, int n)
{
    __shared__ __align__(16) float sw[SW_TOTAL];
    const int tid = threadIdx.x;

    for (int i = tid; i < 64;  i += BLK){ int k = i >> 4, j = i & 15; sw[OFF_W1 + i] = W1[j*4 + k]; }
    for (int i = tid; i < 512; i += BLK){ int k = i >> 5, j = i & 31; sw[OFF_W2 + i] = W2[j*16 + k]; }
    for (int i = tid; i < 512; i += BLK){ int k = i >> 4, j = i & 15; sw[OFF_W3 + i] = W3[j*32 + k]; }
    for (int i = tid; i < 16;  i += BLK) sw[OFF_B1 + i] = b1[i];
    for (int i = tid; i < 32;  i += BLK) sw[OFF_B2 + i] = b2[i];
    for (int i = tid; i < 16;  i += BLK) sw[OFF_B3 + i] = b3[i];
    if (tid == 0) {
        // Heisenberg coefficients (variational RZ drops under |.|^2).
        float c[4], s[4];
#pragma unroll
        for (int i = 0; i < 4; i++) __sincosf(qw[2*i], &s[i], &c[i]);
        float K[30];
        K[0]=+c[0];                 K[1]=-s[0];
        K[2]=+c[0]*c[1];            K[3]=-c[0]*s[1];
        K[4]=+s[0]*c[1];            K[5]=+s[0]*s[1];
        K[6]=+c[0]*c[1]*c[2];       K[7]=-c[0]*c[1]*s[2];
        K[8]=+c[0]*s[1]*c[2];       K[9]=+c[0]*s[1]*s[2];
        K[10]=-s[0]*c[1]*c[2];      K[11]=-s[0]*c[1]*s[2];
        K[12]=-s[0]*s[1]*c[2];      K[13]=-s[0]*s[1]*s[2];
        K[14]=+c[0]*c[1]*c[2]*c[3]; K[15]=-c[0]*c[1]*c[2]*s[3];
        K[16]=+c[0]*c[1]*s[2]*c[3]; K[17]=+c[0]*c[1]*s[2]*s[3];
        K[18]=-c[0]*s[1]*c[2]*c[3]; K[19]=-c[0]*s[1]*c[2]*s[3];
        K[20]=-c[0]*s[1]*s[2]*c[3]; K[21]=-c[0]*s[1]*s[2]*s[3];
        K[22]=+s[0]*c[1]*c[2]*c[3]; K[23]=+s[0]*c[1]*c[2]*s[3];
        K[24]=-s[0]*c[1]*s[2]*c[3]; K[25]=+s[0]*c[1]*s[2]*s[3];
        K[26]=+s[0]*s[1]*c[2]*c[3]; K[27]=+s[0]*s[1]*c[2]*s[3];
        K[28]=+s[0]*s[1]*s[2]*c[3]; K[29]=+s[0]*s[1]*s[2]*s[3];
#pragma unroll
        for (int i = 0; i < 30; i++){ sw[OFF_C + 2*i] = K[i]; sw[OFF_C + 2*i + 1] = K[i]; }
    }
    __syncthreads();

    const int quart = n >> 2;                 // elements b0, +q, +2q, +3q
    const int b0 = blockIdx.x * BLK + tid;
    if (b0 >= quart) return;

    // ---- quantum encoder, pair at a time (defer x loads to limit live regs) ----
    float z[4][4];
    {
        float xr0[8], xr1[8];
        {
            const float4* xv0 = (const float4*)(x + (size_t)b0 * 16);
            const float4* xv1 = (const float4*)(x + (size_t)(b0 + quart) * 16);
            float4 v0 = xv0[0], v1 = xv0[1], v2 = xv1[0], v3 = xv1[1];
            xr0[0]=v0.x; xr0[1]=v0.y; xr0[2]=v0.z; xr0[3]=v0.w;
            xr0[4]=v1.x; xr0[5]=v1.y; xr0[6]=v1.z; xr0[7]=v1.w;
            xr1[0]=v2.x; xr1[1]=v2.y; xr1[2]=v2.z; xr1[3]=v2.w;
            xr1[4]=v3.x; xr1[5]=v3.y; xr1[6]=v3.z; xr1[7]=v3.w;
        }
        P ep[4];
        quantum_pair(xr0, xr1, sw, ep);
#pragma unroll
        for (int i = 0; i < 4; i++) unpack2(ep[i], z[0][i], z[1][i]);
        {
            const float4* xv0 = (const float4*)(x + (size_t)(b0 + 2*quart) * 16);
            const float4* xv1 = (const float4*)(x + (size_t)(b0 + 3*quart) * 16);
            float4 v0 = xv0[0], v1 = xv0[1], v2 = xv1[0], v3 = xv1[1];
            xr0[0]=v0.x; xr0[1]=v0.y; xr0[2]=v0.z; xr0[3]=v0.w;
            xr0[4]=v1.x; xr0[5]=v1.y; xr0[6]=v1.z; xr0[7]=v1.w;
            xr1[0]=v2.x; xr1[1]=v2.y; xr1[2]=v2.z; xr1[3]=v2.w;
            xr1[4]=v3.x; xr1[5]=v3.y; xr1[6]=v3.z; xr1[7]=v3.w;
        }
        quantum_pair(xr0, xr1, sw, ep);
#pragma unroll
        for (int i = 0; i < 4; i++) unpack2(ep[i], z[2][i], z[3][i]);
    }

    // ================= MLP: weights shared by 4 elements; L2->L3 streamed ==============
    const P* B1p = (const P*)(sw + OFF_B1);
    const P* B2p = (const P*)(sw + OFF_B2);
    const P* B3p = (const P*)(sw + OFF_B3);

    // ---- layer 1: 4 -> 16 ----
    float h1[4][16];
    {
        P acc[4][8];
#pragma unroll
        for (int jp = 0; jp < 8; jp++) {
            P bb = B1p[jp];
#pragma unroll
            for (int e = 0; e < 4; e++) acc[e][jp] = bb;
        }
#pragma unroll
        for (int k = 0; k < 4; k++) {
            P d[4];
#pragma unroll
            for (int e = 0; e < 4; e++) d[e] = dupP(z[e][k]);
            const ulonglong2* row = (const ulonglong2*)(sw + OFF_W1 + k*16);
#pragma unroll
            for (int q = 0; q < 4; q++) {
                ulonglong2 u = row[q];
                P w0 = mkP(u.x), w1 = mkP(u.y);
#pragma unroll
                for (int e = 0; e < 4; e++) {
                    acc[e][2*q]   = fma2(w0, d[e], acc[e][2*q]);
                    acc[e][2*q+1] = fma2(w1, d[e], acc[e][2*q+1]);
                }
            }
        }
#pragma unroll
        for (int e = 0; e < 4; e++)
#pragma unroll
            for (int jp = 0; jp < 8; jp++) {
                float lo, hi;
                unpack2(acc[e][jp], lo, hi);
                h1[e][2*jp] = fmaxf(lo, 0.0f); h1[e][2*jp+1] = fmaxf(hi, 0.0f);
            }
    }

    // ---- layers 2+3 streamed: L2 in 4 chunks of 8 neurons, each chunk immediately
    //      ReLU'd and folded into persistent L3 accumulators (h2 never materializes) ----
    P l3[4][8];
#pragma unroll
    for (int jp = 0; jp < 8; jp++) {
        P bb = B3p[jp];
#pragma unroll
        for (int e = 0; e < 4; e++) l3[e][jp] = bb;
    }

#pragma unroll
    for (int c = 0; c < 4; c++) {
        // L2 chunk: 8 neurons (4 neuron-pairs)
        P l2[4][4];
#pragma unroll
        for (int jp = 0; jp < 4; jp++) {
            P bb = B2p[c*4 + jp];
#pragma unroll
            for (int e = 0; e < 4; e++) l2[e][jp] = bb;
        }
#pragma unroll
        for (int k = 0; k < 16; k++) {
            P d[4];
#pragma unroll
            for (int e = 0; e < 4; e++) d[e] = dupP(h1[e][k]);
            const ulonglong2* row = (const ulonglong2*)(sw + OFF_W2 + k*32 + c*8);
#pragma unroll
            for (int q = 0; q < 2; q++) {
                ulonglong2 u = row[q];
                P w0 = mkP(u.x), w1 = mkP(u.y);
#pragma unroll
                for (int e = 0; e < 4; e++) {
                    l2[e][2*q]   = fma2(w0, d[e], l2[e][2*q]);
                    l2[e][2*q+1] = fma2(w1, d[e], l2[e][2*q+1]);
                }
            }
        }
        // ReLU + immediate L3 accumulation, neuron-pair at a time
#pragma unroll
        for (int jp = 0; jp < 4; jp++) {
            const int k3a = c*8 + 2*jp;
            float lo[4], hi[4];
#pragma unroll
            for (int e = 0; e < 4; e++) {
                float l, h;
                unpack2(l2[e][jp], l, h);
                lo[e] = fmaxf(l, 0.0f); hi[e] = fmaxf(h, 0.0f);
            }
            const ulonglong2* rowA = (const ulonglong2*)(sw + OFF_W3 + k3a*16);
            const ulonglong2* rowB = (const ulonglong2*)(sw + OFF_W3 + (k3a+1)*16);
#pragma unroll
            for (int q = 0; q < 4; q++) {
                ulonglong2 uA = rowA[q];
                ulonglong2 uB = rowB[q];
                P wA0 = mkP(uA.x), wA1 = mkP(uA.y);
                P wB0 = mkP(uB.x), wB1 = mkP(uB.y);
#pragma unroll
                for (int e = 0; e < 4; e++) {
                    P dl = dupP(lo[e]), dh = dupP(hi[e]);
                    l3[e][2*q]   = fma2(wA0, dl, l3[e][2*q]);
                    l3[e][2*q+1] = fma2(wA1, dl, l3[e][2*q+1]);
                    l3[e][2*q]   = fma2(wB0, dh, l3[e][2*q]);
                    l3[e][2*q+1] = fma2(wB1, dh, l3[e][2*q+1]);
                }
            }
        }
    }

    // ---- store ----
#pragma unroll
    for (int e = 0; e < 4; e++) {
        float* o = out + (size_t)(b0 + e*quart) * 16;
#pragma unroll
        for (int g = 0; g < 4; g++) {
            float4 v;
            unpack2(l3[e][2*g],   v.x, v.y);
            unpack2(l3[e][2*g+1], v.z, v.w);
            ((float4*)o)[g] = v;
        }
    }
}

extern "C" void kernel_launch(void* const* d_in, const int* in_sizes, int n_in,
                              void* d_out, int out_size)
{
    const float* x  = (const float*)d_in[0];
    const float* qw = (const float*)d_in[1];
    const float* W1 = (const float*)d_in[2];
    const float* b1 = (const float*)d_in[3];
    const float* W2 = (const float*)d_in[4];
    const float* b2 = (const float*)d_in[5];
    const float* W3 = (const float*)d_in[6];
    const float* b3 = (const float*)d_in[7];
    float* out = (float*)d_out;

    const int n = in_sizes[0] / 16;           // B (divisible by 4)
    const int quart = n >> 2;
    const int blocks = (quart + BLK - 1) / BLK;
    hqae_kernel<<<blocks, BLK>>>(x, qw, W1, b1, W2, b2, W3, b3, out, n);
}